// round 1
// baseline (speedup 1.0000x reference)
#include <cuda_runtime.h>

#define HD 128
#define DD 8

// Scratch for the precomputed trace matrix M[k][j] = W2[k][j] * sum_d W1[d][k]*W3[j][d]
__device__ float g_M[HD * HD];

__device__ __forceinline__ float fast_tanh(float x) {
    float y;
    asm("tanh.approx.f32 %0, %1;" : "=f"(y) : "f"(x));
    return y;
}

__global__ void precompute_M_kernel(const float* __restrict__ W1,
                                    const float* __restrict__ W2,
                                    const float* __restrict__ W3) {
    int idx = blockIdx.x * blockDim.x + threadIdx.x;
    if (idx >= HD * HD) return;
    int k = idx >> 7;          // row of W2  (hidden-1 index)
    int j = idx & (HD - 1);    // col of W2  (hidden-2 index)
    float c = 0.0f;
#pragma unroll
    for (int d = 0; d < DD; d++)
        c += W1[d * HD + k] * W3[j * DD + d];
    g_M[idx] = W2[idx] * c;
}

// smem layout (floats): W2s[128*128] | Ms[128*128] | s2s[128*128] | W1s[9*128] | W3s[128*8] | b1s[128] | b2s[128] | b3s[8]
#define SMEM_FLOATS (3 * HD * HD + 9 * HD + HD * DD + HD + HD + DD)
#define SMEM_BYTES  (SMEM_FLOATS * 4)

__global__ __launch_bounds__(128, 1)
void cnf_kernel(const float* __restrict__ z,
                const float* __restrict__ t,
                const float* __restrict__ W1, const float* __restrict__ b1,
                const float* __restrict__ W2, const float* __restrict__ b2,
                const float* __restrict__ W3, const float* __restrict__ b3,
                float* __restrict__ dz_out, float* __restrict__ dlogp_out,
                int B)
{
    extern __shared__ float sm[];
    float* W2s = sm;                  // [k][j] row-major, 16384
    float* Ms  = W2s + HD * HD;       // [k][j] row-major, 16384
    float* s2s = Ms  + HD * HD;       // [j][tid], 16384 (per-thread scratch, no cross-thread use)
    float* W1s = s2s + HD * 128;      // [d][k], 1152 (d = 0..8, row 8 is the t row)
    float* W3s = W1s + 9 * HD;        // [j][d], 1024
    float* b1s = W3s + HD * DD;       // 128
    float* b2s = b1s + HD;            // 128
    float* b3s = b2s + HD;            // 8

    const int tid = threadIdx.x;

    for (int i = tid; i < HD * HD; i += 128) {
        W2s[i] = W2[i];
        Ms[i]  = g_M[i];
    }
    for (int i = tid; i < 9 * HD; i += 128) W1s[i] = W1[i];
    for (int i = tid; i < HD * DD; i += 128) W3s[i] = W3[i];
    if (tid < HD) { b1s[tid] = b1[tid]; b2s[tid] = b2[tid]; }
    if (tid < DD) b3s[tid] = b3[tid];
    __syncthreads();

    const int sample = blockIdx.x * 128 + tid;
    if (sample >= B) return;

    // ---- load z sample (32B aligned) ----
    float zr[DD];
    const float4* zv = (const float4*)(z + (size_t)sample * DD);
    float4 za = zv[0], zb = zv[1];
    zr[0] = za.x; zr[1] = za.y; zr[2] = za.z; zr[3] = za.w;
    zr[4] = zb.x; zr[5] = zb.y; zr[6] = zb.z; zr[7] = zb.w;
    const float tv = t[0];

    // ---- layer 1: h1 = tanh(z @ W1[0:8] + t*W1[8] + b1), kept in registers ----
    float h1[HD];
#pragma unroll
    for (int k = 0; k < HD; k += 4) {
        float4 acc = *(const float4*)&b1s[k];
#pragma unroll
        for (int d = 0; d < DD; d++) {
            float4 w = *(const float4*)&W1s[d * HD + k];
            acc.x += zr[d] * w.x; acc.y += zr[d] * w.y;
            acc.z += zr[d] * w.z; acc.w += zr[d] * w.w;
        }
        float4 w8 = *(const float4*)&W1s[8 * HD + k];
        acc.x += tv * w8.x; acc.y += tv * w8.y;
        acc.z += tv * w8.z; acc.w += tv * w8.w;
        h1[k + 0] = fast_tanh(acc.x);
        h1[k + 1] = fast_tanh(acc.y);
        h1[k + 2] = fast_tanh(acc.z);
        h1[k + 3] = fast_tanh(acc.w);
    }

    float dz[DD];
#pragma unroll
    for (int d = 0; d < DD; d++) dz[d] = b3s[d];

    // ---- pass 1: a2 = h1 @ W2 + b2 ; h2 = tanh(a2); s2 -> smem; dz += h2 @ W3 ----
#pragma unroll 1
    for (int jt = 0; jt < HD; jt += 8) {
        float a[8];
#pragma unroll
        for (int u = 0; u < 8; u++) a[u] = b2s[jt + u];
#pragma unroll
        for (int k = 0; k < HD; k++) {
            float hv = h1[k];
            float4 w0 = *(const float4*)&W2s[k * HD + jt];
            float4 w1 = *(const float4*)&W2s[k * HD + jt + 4];
            a[0] += hv * w0.x; a[1] += hv * w0.y; a[2] += hv * w0.z; a[3] += hv * w0.w;
            a[4] += hv * w1.x; a[5] += hv * w1.y; a[6] += hv * w1.z; a[7] += hv * w1.w;
        }
#pragma unroll
        for (int u = 0; u < 8; u++) {
            float h2 = fast_tanh(a[u]);
            s2s[(jt + u) * 128 + tid] = 1.0f - h2 * h2;
            float4 w3a = *(const float4*)&W3s[(jt + u) * DD + 0];
            float4 w3b = *(const float4*)&W3s[(jt + u) * DD + 4];
            dz[0] += h2 * w3a.x; dz[1] += h2 * w3a.y; dz[2] += h2 * w3a.z; dz[3] += h2 * w3a.w;
            dz[4] += h2 * w3b.x; dz[5] += h2 * w3b.y; dz[6] += h2 * w3b.z; dz[7] += h2 * w3b.w;
        }
    }

    // ---- s1 = 1 - h1^2 (in place) ----
#pragma unroll
    for (int k = 0; k < HD; k++) h1[k] = 1.0f - h1[k] * h1[k];

    // ---- pass 2: trace = s1^T M s2  (u[j] = sum_k s1[k] M[k][j]; trace = sum_j u[j] s2[j]) ----
    float trace = 0.0f;
#pragma unroll 1
    for (int jt = 0; jt < HD; jt += 8) {
        float w[8];
#pragma unroll
        for (int u = 0; u < 8; u++) w[u] = 0.0f;
#pragma unroll
        for (int k = 0; k < HD; k++) {
            float sv = h1[k];
            float4 m0 = *(const float4*)&Ms[k * HD + jt];
            float4 m1 = *(const float4*)&Ms[k * HD + jt + 4];
            w[0] += sv * m0.x; w[1] += sv * m0.y; w[2] += sv * m0.z; w[3] += sv * m0.w;
            w[4] += sv * m1.x; w[5] += sv * m1.y; w[6] += sv * m1.z; w[7] += sv * m1.w;
        }
#pragma unroll
        for (int u = 0; u < 8; u++)
            trace += w[u] * s2s[(jt + u) * 128 + tid];
    }

    // ---- outputs ----
    float4* outv = (float4*)(dz_out + (size_t)sample * DD);
    outv[0] = make_float4(dz[0], dz[1], dz[2], dz[3]);
    outv[1] = make_float4(dz[4], dz[5], dz[6], dz[7]);
    dlogp_out[sample] = -trace;
}

extern "C" void kernel_launch(void* const* d_in, const int* in_sizes, int n_in,
                              void* d_out, int out_size) {
    const float* z  = (const float*)d_in[0];
    // d_in[1] = logp_z (unused by the math: dlogp/dt = -trace only)
    const float* t  = (const float*)d_in[2];
    const float* W1 = (const float*)d_in[3];
    const float* b1 = (const float*)d_in[4];
    const float* W2 = (const float*)d_in[5];
    const float* b2 = (const float*)d_in[6];
    const float* W3 = (const float*)d_in[7];
    const float* b3 = (const float*)d_in[8];

    const int B = in_sizes[0] / DD;
    float* dz_out    = (float*)d_out;            // [B, 8] flattened first
    float* dlogp_out = dz_out + (size_t)B * DD;  // [B, 1] concatenated after

    precompute_M_kernel<<<(HD * HD + 255) / 256, 256>>>(W1, W2, W3);

    cudaFuncSetAttribute(cnf_kernel,
                         cudaFuncAttributeMaxDynamicSharedMemorySize, SMEM_BYTES);
    cnf_kernel<<<(B + 127) / 128, 128, SMEM_BYTES>>>(
        z, t, W1, b1, W2, b2, W3, b3, dz_out, dlogp_out, B);
}